// round 3
// baseline (speedup 1.0000x reference)
#include <cuda_runtime.h>
#include <math.h>

#define Bb 4
#define Mm 4096
#define Dd 768
#define Ee 1536
#define Nn 16
#define KK 3
#define BMr (Bb*Mm)   // 16384 rows

// ---------------- scratch (static device globals; allocation-free) ----------------
__device__ float g_xn   [BMr*Dd];
__device__ float g_xproj[BMr*Ee];   // later reused as gated y
__device__ float g_zs   [BMr*Ee];   // silu(z)
__device__ float g_xpf  [BMr*Ee];
__device__ float g_xpb  [BMr*Ee];
__device__ float g_df   [BMr*Ee];
__device__ float g_dbk  [BMr*Ee];
__device__ float g_yf   [BMr*Ee];
__device__ float g_yb   [BMr*Ee];
__device__ float g_Bpf  [BMr*Nn];
__device__ float g_Cpf  [BMr*Nn];
__device__ float g_Bpb  [BMr*Nn];
__device__ float g_Cpb  [BMr*Nn];
__device__ float g_wcf  [KK*Ee*Ee]; // conv weights repacked [k][o][i]
__device__ float g_wcb  [KK*Ee*Ee];

// ---------------- helpers ----------------
__device__ __forceinline__ float silu_f(float x)     { return x / (1.f + expf(-x)); }
__device__ __forceinline__ float softplus_f(float x) { return (x > 20.f) ? x : log1pf(expf(x)); }

// ---------------- layernorm: one block per row of 768 ----------------
__global__ void ln_kernel(const float* __restrict__ t, const float* __restrict__ g,
                          const float* __restrict__ b, float* __restrict__ xn)
{
    int row = blockIdx.x;
    int tid = threadIdx.x;                 // 256 threads, 3 elems each
    const float* x = t + (size_t)row * Dd;
    float v0 = x[tid], v1 = x[tid + 256], v2 = x[tid + 512];
    float s  = v0 + v1 + v2;
    float sq = v0*v0 + v1*v1 + v2*v2;
    #pragma unroll
    for (int off = 16; off > 0; off >>= 1) {
        s  += __shfl_down_sync(0xffffffffu, s,  off);
        sq += __shfl_down_sync(0xffffffffu, sq, off);
    }
    __shared__ float red[16];
    int warp = tid >> 5, lane = tid & 31;
    if (lane == 0) { red[warp] = s; red[8 + warp] = sq; }
    __syncthreads();
    if (tid == 0) {
        float S = 0.f, Q = 0.f;
        #pragma unroll
        for (int w = 0; w < 8; w++) { S += red[w]; Q += red[8 + w]; }
        red[0] = S; red[8] = Q;
    }
    __syncthreads();
    float mu  = red[0] * (1.f / Dd);
    float var = red[8] * (1.f / Dd) - mu * mu;
    float inv = rsqrtf(var + 1e-5f);
    float* o = xn + (size_t)row * Dd;
    o[tid]       = (v0 - mu) * inv * g[tid]       + b[tid];
    o[tid + 256] = (v1 - mu) * inv * g[tid + 256] + b[tid + 256];
    o[tid + 512] = (v2 - mu) * inv * g[tid + 512] + b[tid + 512];
}

// ---------------- NT SGEMM: C[M,N] = A[M,K] @ W[N,K]^T + bias (+bias2) [ACT] (+resid)
// 128x128x16 tile, 256 threads, 8x8 per thread
template<int ACT>
__global__ void __launch_bounds__(256)
gemm_nt(const float* __restrict__ A, const float* __restrict__ W,
        const float* __restrict__ bias, const float* __restrict__ bias2,
        const float* __restrict__ resid, float* __restrict__ C,
        int Ntot, int Ktot)
{
    __shared__ float As[16][132];
    __shared__ float Ws[16][132];
    int tid  = threadIdx.x;
    int brow = blockIdx.y * 128;
    int bcol = blockIdx.x * 128;
    int lr = tid >> 2;             // 0..63
    int lc = (tid & 3) * 4;        // 0,4,8,12
    int ty = tid >> 4, tx = tid & 15;

    const float* Ap0 = A + (size_t)(brow + lr)      * Ktot + lc;
    const float* Ap1 = A + (size_t)(brow + lr + 64) * Ktot + lc;
    const float* Wp0 = W + (size_t)(bcol + lr)      * Ktot + lc;
    const float* Wp1 = W + (size_t)(bcol + lr + 64) * Ktot + lc;

    float acc[8][8];
    #pragma unroll
    for (int i = 0; i < 8; i++)
        #pragma unroll
        for (int j = 0; j < 8; j++) acc[i][j] = 0.f;

    for (int k0 = 0; k0 < Ktot; k0 += 16) {
        float4 a0 = *(const float4*)(Ap0 + k0);
        float4 a1 = *(const float4*)(Ap1 + k0);
        float4 w0 = *(const float4*)(Wp0 + k0);
        float4 w1 = *(const float4*)(Wp1 + k0);
        __syncthreads();
        As[lc+0][lr] = a0.x; As[lc+1][lr] = a0.y; As[lc+2][lr] = a0.z; As[lc+3][lr] = a0.w;
        As[lc+0][lr+64] = a1.x; As[lc+1][lr+64] = a1.y; As[lc+2][lr+64] = a1.z; As[lc+3][lr+64] = a1.w;
        Ws[lc+0][lr] = w0.x; Ws[lc+1][lr] = w0.y; Ws[lc+2][lr] = w0.z; Ws[lc+3][lr] = w0.w;
        Ws[lc+0][lr+64] = w1.x; Ws[lc+1][lr+64] = w1.y; Ws[lc+2][lr+64] = w1.z; Ws[lc+3][lr+64] = w1.w;
        __syncthreads();
        #pragma unroll
        for (int kk = 0; kk < 16; ++kk) {
            float4 ra0 = *(const float4*)&As[kk][ty*8];
            float4 ra1 = *(const float4*)&As[kk][ty*8 + 4];
            float4 rw0 = *(const float4*)&Ws[kk][tx*8];
            float4 rw1 = *(const float4*)&Ws[kk][tx*8 + 4];
            float ra[8] = {ra0.x,ra0.y,ra0.z,ra0.w, ra1.x,ra1.y,ra1.z,ra1.w};
            float rw[8] = {rw0.x,rw0.y,rw0.z,rw0.w, rw1.x,rw1.y,rw1.z,rw1.w};
            #pragma unroll
            for (int i = 0; i < 8; i++)
                #pragma unroll
                for (int j = 0; j < 8; j++)
                    acc[i][j] = fmaf(ra[i], rw[j], acc[i][j]);
        }
    }
    #pragma unroll
    for (int i = 0; i < 8; i++) {
        int r = brow + ty*8 + i;
        #pragma unroll
        for (int j = 0; j < 8; j++) {
            int c = bcol + tx*8 + j;
            float v = acc[i][j] + bias[c];
            if (bias2) v += bias2[c];
            if (ACT == 1) v = silu_f(v);
            if (ACT == 2) v = softplus_f(v);
            if (resid) v += resid[(size_t)r*Ntot + c];
            C[(size_t)r*Ntot + c] = v;
        }
    }
}

// ---------------- conv weight repack: w[o][i][k] -> out[k][o][i] ----------------
__global__ void repack_conv(const float* __restrict__ w, float* __restrict__ out)
{
    int idx = blockIdx.x * blockDim.x + threadIdx.x;
    if (idx >= Ee*Ee) return;
    int o = idx / Ee, i = idx % Ee;
    #pragma unroll
    for (int k = 0; k < KK; k++)
        out[(size_t)k*Ee*Ee + (size_t)o*Ee + i] = w[((size_t)o*Ee + i)*KK + k];
}

// ---------------- conv-as-GEMM (shifted A gather), fused bias+silu ----------------
__global__ void __launch_bounds__(256)
conv_gemm(const float* __restrict__ X, const float* __restrict__ Wp,
          const float* __restrict__ bias, float* __restrict__ C)
{
    __shared__ float As[16][132];
    __shared__ float Ws[16][132];
    int tid  = threadIdx.x;
    int brow = blockIdx.y * 128;
    int bcol = blockIdx.x * 128;
    int b_ = brow / Mm;
    int m0 = brow % Mm;
    int lr = tid >> 2;
    int lc = (tid & 3) * 4;
    int ty = tid >> 4, tx = tid & 15;

    float acc[8][8];
    #pragma unroll
    for (int i = 0; i < 8; i++)
        #pragma unroll
        for (int j = 0; j < 8; j++) acc[i][j] = 0.f;

    for (int k0 = 0; k0 < KK*Ee; k0 += 16) {
        int seg = k0 / Ee;
        int e0  = k0 % Ee;
        int sh  = seg - 1;
        int mA = m0 + lr + sh;
        int mB = m0 + lr + 64 + sh;
        float4 a0 = (mA >= 0 && mA < Mm)
                  ? *(const float4*)(X + (size_t)(b_*Mm + mA)*Ee + e0 + lc)
                  : make_float4(0.f,0.f,0.f,0.f);
        float4 a1 = (mB >= 0 && mB < Mm)
                  ? *(const float4*)(X + (size_t)(b_*Mm + mB)*Ee + e0 + lc)
                  : make_float4(0.f,0.f,0.f,0.f);
        const float* wseg = Wp + (size_t)seg*Ee*Ee;
        float4 w0 = *(const float4*)(wseg + (size_t)(bcol + lr)     *Ee + e0 + lc);
        float4 w1 = *(const float4*)(wseg + (size_t)(bcol + lr + 64)*Ee + e0 + lc);
        __syncthreads();
        As[lc+0][lr] = a0.x; As[lc+1][lr] = a0.y; As[lc+2][lr] = a0.z; As[lc+3][lr] = a0.w;
        As[lc+0][lr+64] = a1.x; As[lc+1][lr+64] = a1.y; As[lc+2][lr+64] = a1.z; As[lc+3][lr+64] = a1.w;
        Ws[lc+0][lr] = w0.x; Ws[lc+1][lr] = w0.y; Ws[lc+2][lr] = w0.z; Ws[lc+3][lr] = w0.w;
        Ws[lc+0][lr+64] = w1.x; Ws[lc+1][lr+64] = w1.y; Ws[lc+2][lr+64] = w1.z; Ws[lc+3][lr+64] = w1.w;
        __syncthreads();
        #pragma unroll
        for (int kk = 0; kk < 16; ++kk) {
            float4 ra0 = *(const float4*)&As[kk][ty*8];
            float4 ra1 = *(const float4*)&As[kk][ty*8 + 4];
            float4 rw0 = *(const float4*)&Ws[kk][tx*8];
            float4 rw1 = *(const float4*)&Ws[kk][tx*8 + 4];
            float ra[8] = {ra0.x,ra0.y,ra0.z,ra0.w, ra1.x,ra1.y,ra1.z,ra1.w};
            float rw[8] = {rw0.x,rw0.y,rw0.z,rw0.w, rw1.x,rw1.y,rw1.z,rw1.w};
            #pragma unroll
            for (int i = 0; i < 8; i++)
                #pragma unroll
                for (int j = 0; j < 8; j++)
                    acc[i][j] = fmaf(ra[i], rw[j], acc[i][j]);
        }
    }
    #pragma unroll
    for (int i = 0; i < 8; i++) {
        int r = brow + ty*8 + i;
        #pragma unroll
        for (int j = 0; j < 8; j++) {
            int c = bcol + tx*8 + j;
            float v = silu_f(acc[i][j] + bias[c]);
            C[(size_t)r*Ee + c] = v;
        }
    }
}

// ---------------- B/C projections: per-row 16+16 outputs ----------------
__global__ void __launch_bounds__(256)
bc_kernel(const float* __restrict__ X,
          const float* __restrict__ WB, const float* __restrict__ bB,
          const float* __restrict__ WC, const float* __restrict__ bC,
          float* __restrict__ Bp, float* __restrict__ Cp)
{
    __shared__ float sWB[Nn][256];
    __shared__ float sWC[Nn][256];
    int tid = threadIdx.x;
    int row = blockIdx.x * 256 + tid;
    float accB[Nn], accC[Nn];
    #pragma unroll
    for (int n = 0; n < Nn; n++) { accB[n] = 0.f; accC[n] = 0.f; }

    for (int ec = 0; ec < Ee; ec += 256) {
        __syncthreads();
        #pragma unroll
        for (int q = 0; q < 4; q++) {
            int f4 = q * 256 + tid;          // 0..1023 float4 slots = 16 rows * 64 f4
            int n  = f4 >> 6;
            int e4 = (f4 & 63) * 4;
            *(float4*)&sWB[n][e4] = *(const float4*)(WB + (size_t)n*Ee + ec + e4);
            *(float4*)&sWC[n][e4] = *(const float4*)(WC + (size_t)n*Ee + ec + e4);
        }
        __syncthreads();
        for (int e = 0; e < 256; e += 4) {
            float4 xv = *(const float4*)(X + (size_t)row*Ee + ec + e);
            #pragma unroll
            for (int n = 0; n < Nn; n++) {
                float4 wb = *(const float4*)&sWB[n][e];
                float4 wc = *(const float4*)&sWC[n][e];
                accB[n] = fmaf(xv.x, wb.x, accB[n]);
                accB[n] = fmaf(xv.y, wb.y, accB[n]);
                accB[n] = fmaf(xv.z, wb.z, accB[n]);
                accB[n] = fmaf(xv.w, wb.w, accB[n]);
                accC[n] = fmaf(xv.x, wc.x, accC[n]);
                accC[n] = fmaf(xv.y, wc.y, accC[n]);
                accC[n] = fmaf(xv.z, wc.z, accC[n]);
                accC[n] = fmaf(xv.w, wc.w, accC[n]);
            }
        }
    }
    #pragma unroll
    for (int n = 0; n < Nn; n++) {
        Bp[(size_t)row*Nn + n] = accB[n] + bB[n];
        Cp[(size_t)row*Nn + n] = accC[n] + bC[n];
    }
}

// ---------------- scan: both directions in one launch; thread = one e ----------------
__global__ void __launch_bounds__(256)
scan_kernel(const float* __restrict__ Xf, const float* __restrict__ Df,
            const float* __restrict__ Bpf, const float* __restrict__ Cpf,
            const float* __restrict__ Af,  float* __restrict__ Yf,
            const float* __restrict__ Xb, const float* __restrict__ Db,
            const float* __restrict__ Bpb, const float* __restrict__ Cpb,
            const float* __restrict__ Ab,  float* __restrict__ Yb)
{
    int dir = blockIdx.z;
    const float *X, *Dl, *Bp, *Cp, *A;
    float* Y;
    if (dir == 0) { X = Xf; Dl = Df; Bp = Bpf; Cp = Cpf; A = Af; Y = Yf; }
    else          { X = Xb; Dl = Db; Bp = Bpb; Cp = Cpb; A = Ab; Y = Yb; }
    bool rev = (dir == 1);

    int b_  = blockIdx.y;
    int tid = threadIdx.x;
    int e   = blockIdx.x * 256 + tid;
    size_t baseRow = (size_t)b_ * Mm;

    float a[Nn];
    #pragma unroll
    for (int q = 0; q < 4; q++) {
        float4 av = *(const float4*)(A + (size_t)e*Nn + q*4);
        a[q*4+0] = av.x; a[q*4+1] = av.y; a[q*4+2] = av.z; a[q*4+3] = av.w;
    }
    float h[Nn];
    #pragma unroll
    for (int n = 0; n < Nn; n++) h[n] = 0.f;

    __shared__ float sBC[2][8][32];
    int ls = tid >> 5;   // 0..7  step within chunk (for BC loads)
    int ln = tid & 31;   // 0..31 (B:0-15, C:16-31)

    // preload chunk 0
    float xb[8], db[8];
    #pragma unroll
    for (int s = 0; s < 8; s++) {
        int m = rev ? (Mm - 1 - s) : s;
        size_t idx = (baseRow + m) * Ee + e;
        xb[s] = X[idx]; db[s] = Dl[idx];
    }
    {
        int m = rev ? (Mm - 1 - ls) : ls;
        sBC[0][ls][ln] = (ln < Nn) ? Bp[(baseRow + m)*Nn + ln]
                                   : Cp[(baseRow + m)*Nn + (ln - Nn)];
    }
    __syncthreads();

    const int NCH = Mm / 8; // 512 chunks
    for (int c = 0; c < NCH; ++c) {
        int buf = c & 1;
        float nx[8], nd[8], nbc = 0.f;
        bool more = (c + 1 < NCH);
        if (more) {
            #pragma unroll
            for (int s = 0; s < 8; s++) {
                int t = (c + 1) * 8 + s;
                int m = rev ? (Mm - 1 - t) : t;
                size_t idx = (baseRow + m) * Ee + e;
                nx[s] = X[idx]; nd[s] = Dl[idx];
            }
            int t = (c + 1) * 8 + ls;
            int m = rev ? (Mm - 1 - t) : t;
            nbc = (ln < Nn) ? Bp[(baseRow + m)*Nn + ln]
                            : Cp[(baseRow + m)*Nn + (ln - Nn)];
        }
        #pragma unroll
        for (int s = 0; s < 8; s++) {
            float dv = db[s], xv = xb[s];
            float dx = dv * xv;
            float yv = 0.f;
            #pragma unroll
            for (int n = 0; n < Nn; n++) {
                float Bn = sBC[buf][s][n];
                float Cn = sBC[buf][s][Nn + n];
                h[n] = fmaf(dv * a[n], h[n], dx * Bn);
                yv   = fmaf(h[n], Cn, yv);
            }
            int t = c * 8 + s;
            int m = rev ? (Mm - 1 - t) : t;
            Y[(baseRow + m) * Ee + e] = yv;
        }
        if (more) {
            #pragma unroll
            for (int s = 0; s < 8; s++) { xb[s] = nx[s]; db[s] = nd[s]; }
            sBC[buf ^ 1][ls][ln] = nbc;
        }
        __syncthreads();
    }
}

// ---------------- gate multiply: y = (yf + yb) * silu(z) (z already silu'd) --------
__global__ void mul_kernel(const float4* __restrict__ a, const float4* __restrict__ b,
                           const float4* __restrict__ z, float4* __restrict__ o, int n4)
{
    for (int i = blockIdx.x * blockDim.x + threadIdx.x; i < n4; i += gridDim.x * blockDim.x) {
        float4 A = a[i], Bv = b[i], Z = z[i], O;
        O.x = (A.x + Bv.x) * Z.x;
        O.y = (A.y + Bv.y) * Z.y;
        O.z = (A.z + Bv.z) * Z.z;
        O.w = (A.w + Bv.w) * Z.w;
        o[i] = O;
    }
}

// ---------------- launch ----------------
extern "C" void kernel_launch(void* const* d_in, const int* in_sizes, int n_in,
                              void* d_out, int out_size)
{
    const float* t    = (const float*)d_in[0];
    const float* ln_g = (const float*)d_in[1];
    const float* ln_b = (const float*)d_in[2];
    const float* Wx   = (const float*)d_in[3];
    const float* bx   = (const float*)d_in[4];
    const float* Wz   = (const float*)d_in[5];
    const float* bz   = (const float*)d_in[6];
    const float* Wcf  = (const float*)d_in[7];
    const float* bcf  = (const float*)d_in[8];
    const float* Wcb  = (const float*)d_in[9];
    const float* bcb  = (const float*)d_in[10];
    const float* WBf  = (const float*)d_in[11];
    const float* bBf  = (const float*)d_in[12];
    const float* WCf  = (const float*)d_in[13];
    const float* bCf  = (const float*)d_in[14];
    const float* WDf  = (const float*)d_in[15];
    const float* bDf  = (const float*)d_in[16];
    const float* WBb  = (const float*)d_in[17];
    const float* bBb  = (const float*)d_in[18];
    const float* WCb  = (const float*)d_in[19];
    const float* bCb  = (const float*)d_in[20];
    const float* WDb  = (const float*)d_in[21];
    const float* bDb  = (const float*)d_in[22];
    const float* Abf  = (const float*)d_in[23];
    const float* Abb  = (const float*)d_in[24];
    const float* dbf  = (const float*)d_in[25];
    const float* dbb  = (const float*)d_in[26];
    const float* WT   = (const float*)d_in[27];
    const float* bT   = (const float*)d_in[28];
    float* out = (float*)d_out;

    void *p_xn, *p_xproj, *p_zs, *p_xpf, *p_xpb, *p_df, *p_dbk, *p_yf, *p_yb;
    void *p_Bpf, *p_Cpf, *p_Bpb, *p_Cpb, *p_wcf, *p_wcb;
    cudaGetSymbolAddress(&p_xn, g_xn);
    cudaGetSymbolAddress(&p_xproj, g_xproj);
    cudaGetSymbolAddress(&p_zs, g_zs);
    cudaGetSymbolAddress(&p_xpf, g_xpf);
    cudaGetSymbolAddress(&p_xpb, g_xpb);
    cudaGetSymbolAddress(&p_df, g_df);
    cudaGetSymbolAddress(&p_dbk, g_dbk);
    cudaGetSymbolAddress(&p_yf, g_yf);
    cudaGetSymbolAddress(&p_yb, g_yb);
    cudaGetSymbolAddress(&p_Bpf, g_Bpf);
    cudaGetSymbolAddress(&p_Cpf, g_Cpf);
    cudaGetSymbolAddress(&p_Bpb, g_Bpb);
    cudaGetSymbolAddress(&p_Cpb, g_Cpb);
    cudaGetSymbolAddress(&p_wcf, g_wcf);
    cudaGetSymbolAddress(&p_wcb, g_wcb);

    float* xn    = (float*)p_xn;
    float* xproj = (float*)p_xproj;
    float* zs    = (float*)p_zs;
    float* xpf   = (float*)p_xpf;
    float* xpb   = (float*)p_xpb;
    float* df    = (float*)p_df;
    float* dbk   = (float*)p_dbk;
    float* yf    = (float*)p_yf;
    float* yb    = (float*)p_yb;
    float* Bpf   = (float*)p_Bpf;
    float* Cpf   = (float*)p_Cpf;
    float* Bpb   = (float*)p_Bpb;
    float* Cpb   = (float*)p_Cpb;
    float* wcf   = (float*)p_wcf;
    float* wcb   = (float*)p_wcb;

    // 1. layernorm
    ln_kernel<<<BMr, 256>>>(t, ln_g, ln_b, xn);

    // 2. x_proj and silu(z)
    dim3 gEB(Ee/128, BMr/128);
    gemm_nt<0><<<gEB, 256>>>(xn, Wx, bx, nullptr, nullptr, xproj, Ee, Dd);
    gemm_nt<1><<<gEB, 256>>>(xn, Wz, bz, nullptr, nullptr, zs,    Ee, Dd);

    // 3. conv weight repack + convs (fused bias + silu)
    repack_conv<<<(Ee*Ee + 255)/256, 256>>>(Wcf, wcf);
    repack_conv<<<(Ee*Ee + 255)/256, 256>>>(Wcb, wcb);
    conv_gemm<<<gEB, 256>>>(xproj, wcf, bcf, xpf);
    conv_gemm<<<gEB, 256>>>(xproj, wcb, bcb, xpb);

    // 4. B/C projections
    bc_kernel<<<BMr/256, 256>>>(xpf, WBf, bBf, WCf, bCf, Bpf, Cpf);
    bc_kernel<<<BMr/256, 256>>>(xpb, WBb, bBb, WCb, bCb, Bpb, Cpb);

    // 5. Delta (softplus)
    gemm_nt<2><<<gEB, 256>>>(xpf, WDf, bDf, dbf, nullptr, df,  Ee, Ee);
    gemm_nt<2><<<gEB, 256>>>(xpb, WDb, bDb, dbb, nullptr, dbk, Ee, Ee);

    // 6. scans (both directions in one launch)
    scan_kernel<<<dim3(Ee/256, Bb, 2), 256>>>(xpf, df, Bpf, Cpf, Abf, yf,
                                              xpb, dbk, Bpb, Cpb, Abb, yb);

    // 7. gate multiply (reuse xproj as gated y)
    mul_kernel<<<2048, 256>>>((const float4*)yf, (const float4*)yb,
                              (const float4*)zs, (float4*)xproj,
                              (BMr * Ee) / 4);

    // 8. final projection + residual
    gemm_nt<0><<<dim3(Dd/128, BMr/128), 256>>>(xproj, WT, bT, nullptr, t, out, Dd, Ee);
}

// round 4
// speedup vs baseline: 2.4614x; 2.4614x over previous
#include <cuda_runtime.h>
#include <math.h>
#include <stdint.h>

#define Bb 4
#define Mm 4096
#define Dd 768
#define Ee 1536
#define Nn 16
#define KK 3
#define BMr (Bb*Mm)   // 16384 rows

// ---------------- scratch (static device globals; allocation-free) ----------------
__device__ float g_xn   [BMr*Dd];
__device__ float g_xproj[BMr*Ee];   // later reused as gated y
__device__ float g_zs   [BMr*Ee];   // silu(z)
__device__ float g_xpf  [BMr*Ee];
__device__ float g_xpb  [BMr*Ee];
__device__ float g_df   [BMr*Ee];
__device__ float g_dbk  [BMr*Ee];
__device__ float g_yf   [BMr*Ee];
__device__ float g_yb   [BMr*Ee];
__device__ float g_Bpf  [BMr*Nn];
__device__ float g_Cpf  [BMr*Nn];
__device__ float g_Bpb  [BMr*Nn];
__device__ float g_Cpb  [BMr*Nn];
__device__ float g_wcf  [KK*Ee*Ee]; // conv weights repacked [k][o][i]
__device__ float g_wcb  [KK*Ee*Ee];

// ---------------- helpers ----------------
__device__ __forceinline__ float silu_f(float x)     { return x / (1.f + expf(-x)); }
__device__ __forceinline__ float softplus_f(float x) { return (x > 20.f) ? x : log1pf(expf(x)); }

__device__ __forceinline__ uint32_t f2tf32(float x) {
    uint32_t r;
    asm("cvt.rna.tf32.f32 %0, %1;" : "=r"(r) : "f"(x));
    return r;
}

__device__ __forceinline__ void mma_tf32(float* c, const uint32_t* a, const uint32_t* b) {
    asm volatile(
        "mma.sync.aligned.m16n8k8.row.col.f32.tf32.tf32.f32 "
        "{%0,%1,%2,%3}, {%4,%5,%6,%7}, {%8,%9}, {%0,%1,%2,%3};\n"
        : "+f"(c[0]), "+f"(c[1]), "+f"(c[2]), "+f"(c[3])
        : "r"(a[0]), "r"(a[1]), "r"(a[2]), "r"(a[3]),
          "r"(b[0]), "r"(b[1]));
}

// ---------------- layernorm: one block per row of 768 ----------------
__global__ void ln_kernel(const float* __restrict__ t, const float* __restrict__ g,
                          const float* __restrict__ b, float* __restrict__ xn)
{
    int row = blockIdx.x;
    int tid = threadIdx.x;                 // 256 threads, 3 elems each
    const float* x = t + (size_t)row * Dd;
    float v0 = x[tid], v1 = x[tid + 256], v2 = x[tid + 512];
    float s  = v0 + v1 + v2;
    float sq = v0*v0 + v1*v1 + v2*v2;
    #pragma unroll
    for (int off = 16; off > 0; off >>= 1) {
        s  += __shfl_down_sync(0xffffffffu, s,  off);
        sq += __shfl_down_sync(0xffffffffu, sq, off);
    }
    __shared__ float red[16];
    int warp = tid >> 5, lane = tid & 31;
    if (lane == 0) { red[warp] = s; red[8 + warp] = sq; }
    __syncthreads();
    if (tid == 0) {
        float S = 0.f, Q = 0.f;
        #pragma unroll
        for (int w = 0; w < 8; w++) { S += red[w]; Q += red[8 + w]; }
        red[0] = S; red[8] = Q;
    }
    __syncthreads();
    float mu  = red[0] * (1.f / Dd);
    float var = red[8] * (1.f / Dd) - mu * mu;
    float inv = rsqrtf(var + 1e-5f);
    float* o = xn + (size_t)row * Dd;
    o[tid]       = (v0 - mu) * inv * g[tid]       + b[tid];
    o[tid + 256] = (v1 - mu) * inv * g[tid + 256] + b[tid + 256];
    o[tid + 512] = (v2 - mu) * inv * g[tid + 512] + b[tid + 512];
}

// ================= tf32 tensor-core NT GEMM =================
// C[M,N] = A[M,K] @ W[N,K]^T + bias (+bias2) [ACT] (+resid)
// 128x128x16 tile, 256 threads, warp grid 4(row)x2(col), per warp 32x64
// smem layout [m][20]/[n][20] words: conflict-free STS.128 and fragment LDS.
template<int ACT>
__global__ void __launch_bounds__(256)
gemm_tc(const float* __restrict__ A, const float* __restrict__ W,
        const float* __restrict__ bias, const float* __restrict__ bias2,
        const float* __restrict__ resid, float* __restrict__ C,
        int Ntot, int Ktot)
{
    __shared__ uint32_t As[128][20];
    __shared__ uint32_t Bs[128][20];
    int tid  = threadIdx.x;
    int brow = blockIdx.y * 128;
    int bcol = blockIdx.x * 128;
    int w  = tid >> 5, l = tid & 31;
    int rb = (w & 3) * 32;         // warp row base
    int cb = (w >> 2) * 64;        // warp col base
    int g  = l >> 2, tg = l & 3;
    int lr = tid >> 2;             // 0..63
    int lc = (tid & 3) * 4;        // k offset 0,4,8,12

    const float* Ap0 = A + (size_t)(brow + lr)      * Ktot + lc;
    const float* Ap1 = A + (size_t)(brow + lr + 64) * Ktot + lc;
    const float* Wp0 = W + (size_t)(bcol + lr)      * Ktot + lc;
    const float* Wp1 = W + (size_t)(bcol + lr + 64) * Ktot + lc;

    float acc[2][8][4];
    #pragma unroll
    for (int i = 0; i < 2; i++)
        #pragma unroll
        for (int j = 0; j < 8; j++)
            #pragma unroll
            for (int q = 0; q < 4; q++) acc[i][j][q] = 0.f;

    float4 pa0 = *(const float4*)(Ap0);
    float4 pa1 = *(const float4*)(Ap1);
    float4 pw0 = *(const float4*)(Wp0);
    float4 pw1 = *(const float4*)(Wp1);

    for (int k0 = 0; k0 < Ktot; k0 += 16) {
        __syncthreads();
        {
            uint4 q;
            q.x = f2tf32(pa0.x); q.y = f2tf32(pa0.y); q.z = f2tf32(pa0.z); q.w = f2tf32(pa0.w);
            *(uint4*)&As[lr][lc] = q;
            q.x = f2tf32(pa1.x); q.y = f2tf32(pa1.y); q.z = f2tf32(pa1.z); q.w = f2tf32(pa1.w);
            *(uint4*)&As[lr + 64][lc] = q;
            q.x = f2tf32(pw0.x); q.y = f2tf32(pw0.y); q.z = f2tf32(pw0.z); q.w = f2tf32(pw0.w);
            *(uint4*)&Bs[lr][lc] = q;
            q.x = f2tf32(pw1.x); q.y = f2tf32(pw1.y); q.z = f2tf32(pw1.z); q.w = f2tf32(pw1.w);
            *(uint4*)&Bs[lr + 64][lc] = q;
        }
        __syncthreads();
        if (k0 + 16 < Ktot) {
            pa0 = *(const float4*)(Ap0 + k0 + 16);
            pa1 = *(const float4*)(Ap1 + k0 + 16);
            pw0 = *(const float4*)(Wp0 + k0 + 16);
            pw1 = *(const float4*)(Wp1 + k0 + 16);
        }
        #pragma unroll
        for (int kk = 0; kk < 16; kk += 8) {
            uint32_t af[2][4], bf[8][2];
            #pragma unroll
            for (int mt = 0; mt < 2; mt++) {
                int r = rb + mt * 16 + g;
                af[mt][0] = As[r    ][kk + tg];
                af[mt][1] = As[r + 8][kk + tg];
                af[mt][2] = As[r    ][kk + tg + 4];
                af[mt][3] = As[r + 8][kk + tg + 4];
            }
            #pragma unroll
            for (int nt = 0; nt < 8; nt++) {
                int n = cb + nt * 8 + g;
                bf[nt][0] = Bs[n][kk + tg];
                bf[nt][1] = Bs[n][kk + tg + 4];
            }
            #pragma unroll
            for (int mt = 0; mt < 2; mt++)
                #pragma unroll
                for (int nt = 0; nt < 8; nt++)
                    mma_tf32(acc[mt][nt], af[mt], bf[nt]);
        }
    }

    // epilogue
    #pragma unroll
    for (int mt = 0; mt < 2; mt++) {
        int r0 = brow + rb + mt * 16 + g;
        #pragma unroll
        for (int nt = 0; nt < 8; nt++) {
            int col = bcol + cb + nt * 8 + 2 * tg;
            float b0 = bias[col], b1 = bias[col + 1];
            if (bias2) { b0 += bias2[col]; b1 += bias2[col + 1]; }
            float v0 = acc[mt][nt][0] + b0;
            float v1 = acc[mt][nt][1] + b1;
            float v2 = acc[mt][nt][2] + b0;
            float v3 = acc[mt][nt][3] + b1;
            if (ACT == 1) { v0 = silu_f(v0); v1 = silu_f(v1); v2 = silu_f(v2); v3 = silu_f(v3); }
            if (ACT == 2) { v0 = softplus_f(v0); v1 = softplus_f(v1); v2 = softplus_f(v2); v3 = softplus_f(v3); }
            if (resid) {
                v0 += resid[(size_t)r0 * Ntot + col];
                v1 += resid[(size_t)r0 * Ntot + col + 1];
                v2 += resid[(size_t)(r0 + 8) * Ntot + col];
                v3 += resid[(size_t)(r0 + 8) * Ntot + col + 1];
            }
            *(float2*)&C[(size_t)r0 * Ntot + col]       = make_float2(v0, v1);
            *(float2*)&C[(size_t)(r0 + 8) * Ntot + col] = make_float2(v2, v3);
        }
    }
}

// ---------------- conv weight repack: w[o][i][k] -> out[k][o][i] ----------------
__global__ void repack_conv(const float* __restrict__ w, float* __restrict__ out)
{
    int idx = blockIdx.x * blockDim.x + threadIdx.x;
    if (idx >= Ee*Ee) return;
    int o = idx / Ee, i = idx % Ee;
    #pragma unroll
    for (int k = 0; k < KK; k++)
        out[(size_t)k*Ee*Ee + (size_t)o*Ee + i] = w[((size_t)o*Ee + i)*KK + k];
}

// ---------------- conv-as-GEMM (shifted A gather) tf32 mma, fused bias+silu ------
__global__ void __launch_bounds__(256)
conv_tc(const float* __restrict__ X, const float* __restrict__ Wp,
        const float* __restrict__ bias, float* __restrict__ C)
{
    __shared__ uint32_t As[128][20];
    __shared__ uint32_t Bs[128][20];
    int tid  = threadIdx.x;
    int brow = blockIdx.y * 128;
    int bcol = blockIdx.x * 128;
    int b_ = brow / Mm;
    int m0 = brow % Mm;
    int w  = tid >> 5, l = tid & 31;
    int rb = (w & 3) * 32;
    int cb = (w >> 2) * 64;
    int g  = l >> 2, tg = l & 3;
    int lr = tid >> 2;
    int lc = (tid & 3) * 4;

    float acc[2][8][4];
    #pragma unroll
    for (int i = 0; i < 2; i++)
        #pragma unroll
        for (int j = 0; j < 8; j++)
            #pragma unroll
            for (int q = 0; q < 4; q++) acc[i][j][q] = 0.f;

    float4 pa0, pa1, pw0, pw1;
    {
        int seg = 0, e0 = 0, sh = -1;
        int mA = m0 + lr + sh;
        int mB = m0 + lr + 64 + sh;
        pa0 = (mA >= 0 && mA < Mm)
            ? *(const float4*)(X + (size_t)(b_*Mm + mA)*Ee + e0 + lc)
            : make_float4(0.f,0.f,0.f,0.f);
        pa1 = (mB >= 0 && mB < Mm)
            ? *(const float4*)(X + (size_t)(b_*Mm + mB)*Ee + e0 + lc)
            : make_float4(0.f,0.f,0.f,0.f);
        const float* wseg = Wp + (size_t)seg*Ee*Ee;
        pw0 = *(const float4*)(wseg + (size_t)(bcol + lr)     *Ee + e0 + lc);
        pw1 = *(const float4*)(wseg + (size_t)(bcol + lr + 64)*Ee + e0 + lc);
    }

    for (int k0 = 0; k0 < KK*Ee; k0 += 16) {
        __syncthreads();
        {
            uint4 q;
            q.x = f2tf32(pa0.x); q.y = f2tf32(pa0.y); q.z = f2tf32(pa0.z); q.w = f2tf32(pa0.w);
            *(uint4*)&As[lr][lc] = q;
            q.x = f2tf32(pa1.x); q.y = f2tf32(pa1.y); q.z = f2tf32(pa1.z); q.w = f2tf32(pa1.w);
            *(uint4*)&As[lr + 64][lc] = q;
            q.x = f2tf32(pw0.x); q.y = f2tf32(pw0.y); q.z = f2tf32(pw0.z); q.w = f2tf32(pw0.w);
            *(uint4*)&Bs[lr][lc] = q;
            q.x = f2tf32(pw1.x); q.y = f2tf32(pw1.y); q.z = f2tf32(pw1.z); q.w = f2tf32(pw1.w);
            *(uint4*)&Bs[lr + 64][lc] = q;
        }
        __syncthreads();
        int k1 = k0 + 16;
        if (k1 < KK*Ee) {
            int seg = k1 / Ee;
            int e0  = k1 % Ee;
            int sh  = seg - 1;
            int mA = m0 + lr + sh;
            int mB = m0 + lr + 64 + sh;
            pa0 = (mA >= 0 && mA < Mm)
                ? *(const float4*)(X + (size_t)(b_*Mm + mA)*Ee + e0 + lc)
                : make_float4(0.f,0.f,0.f,0.f);
            pa1 = (mB >= 0 && mB < Mm)
                ? *(const float4*)(X + (size_t)(b_*Mm + mB)*Ee + e0 + lc)
                : make_float4(0.f,0.f,0.f,0.f);
            const float* wseg = Wp + (size_t)seg*Ee*Ee;
            pw0 = *(const float4*)(wseg + (size_t)(bcol + lr)     *Ee + e0 + lc);
            pw1 = *(const float4*)(wseg + (size_t)(bcol + lr + 64)*Ee + e0 + lc);
        }
        #pragma unroll
        for (int kk = 0; kk < 16; kk += 8) {
            uint32_t af[2][4], bf[8][2];
            #pragma unroll
            for (int mt = 0; mt < 2; mt++) {
                int r = rb + mt * 16 + g;
                af[mt][0] = As[r    ][kk + tg];
                af[mt][1] = As[r + 8][kk + tg];
                af[mt][2] = As[r    ][kk + tg + 4];
                af[mt][3] = As[r + 8][kk + tg + 4];
            }
            #pragma unroll
            for (int nt = 0; nt < 8; nt++) {
                int n = cb + nt * 8 + g;
                bf[nt][0] = Bs[n][kk + tg];
                bf[nt][1] = Bs[n][kk + tg + 4];
            }
            #pragma unroll
            for (int mt = 0; mt < 2; mt++)
                #pragma unroll
                for (int nt = 0; nt < 8; nt++)
                    mma_tf32(acc[mt][nt], af[mt], bf[nt]);
        }
    }

    #pragma unroll
    for (int mt = 0; mt < 2; mt++) {
        int r0 = brow + rb + mt * 16 + g;
        #pragma unroll
        for (int nt = 0; nt < 8; nt++) {
            int col = bcol + cb + nt * 8 + 2 * tg;
            float b0 = bias[col], b1 = bias[col + 1];
            float v0 = silu_f(acc[mt][nt][0] + b0);
            float v1 = silu_f(acc[mt][nt][1] + b1);
            float v2 = silu_f(acc[mt][nt][2] + b0);
            float v3 = silu_f(acc[mt][nt][3] + b1);
            *(float2*)&C[(size_t)r0 * Ee + col]       = make_float2(v0, v1);
            *(float2*)&C[(size_t)(r0 + 8) * Ee + col] = make_float2(v2, v3);
        }
    }
}

// ---------------- B/C projections: per-row 16+16 outputs ----------------
__global__ void __launch_bounds__(256)
bc_kernel(const float* __restrict__ X,
          const float* __restrict__ WB, const float* __restrict__ bB,
          const float* __restrict__ WC, const float* __restrict__ bC,
          float* __restrict__ Bp, float* __restrict__ Cp)
{
    __shared__ float sWB[Nn][256];
    __shared__ float sWC[Nn][256];
    int tid = threadIdx.x;
    int row = blockIdx.x * 256 + tid;
    float accB[Nn], accC[Nn];
    #pragma unroll
    for (int n = 0; n < Nn; n++) { accB[n] = 0.f; accC[n] = 0.f; }

    for (int ec = 0; ec < Ee; ec += 256) {
        __syncthreads();
        #pragma unroll
        for (int q = 0; q < 4; q++) {
            int f4 = q * 256 + tid;          // 0..1023 float4 slots = 16 rows * 64 f4
            int n  = f4 >> 6;
            int e4 = (f4 & 63) * 4;
            *(float4*)&sWB[n][e4] = *(const float4*)(WB + (size_t)n*Ee + ec + e4);
            *(float4*)&sWC[n][e4] = *(const float4*)(WC + (size_t)n*Ee + ec + e4);
        }
        __syncthreads();
        for (int e = 0; e < 256; e += 4) {
            float4 xv = *(const float4*)(X + (size_t)row*Ee + ec + e);
            #pragma unroll
            for (int n = 0; n < Nn; n++) {
                float4 wb = *(const float4*)&sWB[n][e];
                float4 wc = *(const float4*)&sWC[n][e];
                accB[n] = fmaf(xv.x, wb.x, accB[n]);
                accB[n] = fmaf(xv.y, wb.y, accB[n]);
                accB[n] = fmaf(xv.z, wb.z, accB[n]);
                accB[n] = fmaf(xv.w, wb.w, accB[n]);
                accC[n] = fmaf(xv.x, wc.x, accC[n]);
                accC[n] = fmaf(xv.y, wc.y, accC[n]);
                accC[n] = fmaf(xv.z, wc.z, accC[n]);
                accC[n] = fmaf(xv.w, wc.w, accC[n]);
            }
        }
    }
    #pragma unroll
    for (int n = 0; n < Nn; n++) {
        Bp[(size_t)row*Nn + n] = accB[n] + bB[n];
        Cp[(size_t)row*Nn + n] = accC[n] + bC[n];
    }
}

// ---------------- scan: both directions in one launch; thread = one e ----------------
__global__ void __launch_bounds__(256)
scan_kernel(const float* __restrict__ Xf, const float* __restrict__ Df,
            const float* __restrict__ Bpf, const float* __restrict__ Cpf,
            const float* __restrict__ Af,  float* __restrict__ Yf,
            const float* __restrict__ Xb, const float* __restrict__ Db,
            const float* __restrict__ Bpb, const float* __restrict__ Cpb,
            const float* __restrict__ Ab,  float* __restrict__ Yb)
{
    int dir = blockIdx.z;
    const float *X, *Dl, *Bp, *Cp, *A;
    float* Y;
    if (dir == 0) { X = Xf; Dl = Df; Bp = Bpf; Cp = Cpf; A = Af; Y = Yf; }
    else          { X = Xb; Dl = Db; Bp = Bpb; Cp = Cpb; A = Ab; Y = Yb; }
    bool rev = (dir == 1);

    int b_  = blockIdx.y;
    int tid = threadIdx.x;
    int e   = blockIdx.x * 256 + tid;
    size_t baseRow = (size_t)b_ * Mm;

    float a[Nn];
    #pragma unroll
    for (int q = 0; q < 4; q++) {
        float4 av = *(const float4*)(A + (size_t)e*Nn + q*4);
        a[q*4+0] = av.x; a[q*4+1] = av.y; a[q*4+2] = av.z; a[q*4+3] = av.w;
    }
    float h[Nn];
    #pragma unroll
    for (int n = 0; n < Nn; n++) h[n] = 0.f;

    __shared__ float sBC[2][8][32];
    int ls = tid >> 5;   // 0..7  step within chunk (for BC loads)
    int ln = tid & 31;   // 0..31 (B:0-15, C:16-31)

    // preload chunk 0
    float xb[8], db[8];
    #pragma unroll
    for (int s = 0; s < 8; s++) {
        int m = rev ? (Mm - 1 - s) : s;
        size_t idx = (baseRow + m) * Ee + e;
        xb[s] = X[idx]; db[s] = Dl[idx];
    }
    {
        int m = rev ? (Mm - 1 - ls) : ls;
        sBC[0][ls][ln] = (ln < Nn) ? Bp[(baseRow + m)*Nn + ln]
                                   : Cp[(baseRow + m)*Nn + (ln - Nn)];
    }
    __syncthreads();

    const int NCH = Mm / 8; // 512 chunks
    for (int c = 0; c < NCH; ++c) {
        int buf = c & 1;
        float nx[8], nd[8], nbc = 0.f;
        bool more = (c + 1 < NCH);
        if (more) {
            #pragma unroll
            for (int s = 0; s < 8; s++) {
                int t = (c + 1) * 8 + s;
                int m = rev ? (Mm - 1 - t) : t;
                size_t idx = (baseRow + m) * Ee + e;
                nx[s] = X[idx]; nd[s] = Dl[idx];
            }
            int t = (c + 1) * 8 + ls;
            int m = rev ? (Mm - 1 - t) : t;
            nbc = (ln < Nn) ? Bp[(baseRow + m)*Nn + ln]
                            : Cp[(baseRow + m)*Nn + (ln - Nn)];
        }
        #pragma unroll
        for (int s = 0; s < 8; s++) {
            float dv = db[s], xv = xb[s];
            float dx = dv * xv;
            float yv0 = 0.f, yv1 = 0.f;
            #pragma unroll
            for (int n = 0; n < Nn; n += 2) {
                float Bn0 = sBC[buf][s][n];
                float Cn0 = sBC[buf][s][Nn + n];
                float Bn1 = sBC[buf][s][n + 1];
                float Cn1 = sBC[buf][s][Nn + n + 1];
                h[n]     = fmaf(dv * a[n],     h[n],     dx * Bn0);
                h[n + 1] = fmaf(dv * a[n + 1], h[n + 1], dx * Bn1);
                yv0 = fmaf(h[n],     Cn0, yv0);
                yv1 = fmaf(h[n + 1], Cn1, yv1);
            }
            int t = c * 8 + s;
            int m = rev ? (Mm - 1 - t) : t;
            Y[(baseRow + m) * Ee + e] = yv0 + yv1;
        }
        if (more) {
            #pragma unroll
            for (int s = 0; s < 8; s++) { xb[s] = nx[s]; db[s] = nd[s]; }
            sBC[buf ^ 1][ls][ln] = nbc;
        }
        __syncthreads();
    }
}

// ---------------- gate multiply: y = (yf + yb) * silu(z) (z already silu'd) --------
__global__ void mul_kernel(const float4* __restrict__ a, const float4* __restrict__ b,
                           const float4* __restrict__ z, float4* __restrict__ o, int n4)
{
    for (int i = blockIdx.x * blockDim.x + threadIdx.x; i < n4; i += gridDim.x * blockDim.x) {
        float4 A = a[i], Bv = b[i], Z = z[i], O;
        O.x = (A.x + Bv.x) * Z.x;
        O.y = (A.y + Bv.y) * Z.y;
        O.z = (A.z + Bv.z) * Z.z;
        O.w = (A.w + Bv.w) * Z.w;
        o[i] = O;
    }
}

// ---------------- launch ----------------
extern "C" void kernel_launch(void* const* d_in, const int* in_sizes, int n_in,
                              void* d_out, int out_size)
{
    const float* t    = (const float*)d_in[0];
    const float* ln_g = (const float*)d_in[1];
    const float* ln_b = (const float*)d_in[2];
    const float* Wx   = (const float*)d_in[3];
    const float* bx   = (const float*)d_in[4];
    const float* Wz   = (const float*)d_in[5];
    const float* bz   = (const float*)d_in[6];
    const float* Wcf  = (const float*)d_in[7];
    const float* bcf  = (const float*)d_in[8];
    const float* Wcb  = (const float*)d_in[9];
    const float* bcb  = (const float*)d_in[10];
    const float* WBf  = (const float*)d_in[11];
    const float* bBf  = (const float*)d_in[12];
    const float* WCf  = (const float*)d_in[13];
    const float* bCf  = (const float*)d_in[14];
    const float* WDf  = (const float*)d_in[15];
    const float* bDf  = (const float*)d_in[16];
    const float* WBb  = (const float*)d_in[17];
    const float* bBb  = (const float*)d_in[18];
    const float* WCb  = (const float*)d_in[19];
    const float* bCb  = (const float*)d_in[20];
    const float* WDb  = (const float*)d_in[21];
    const float* bDb  = (const float*)d_in[22];
    const float* Abf  = (const float*)d_in[23];
    const float* Abb  = (const float*)d_in[24];
    const float* dbf  = (const float*)d_in[25];
    const float* dbb  = (const float*)d_in[26];
    const float* WT   = (const float*)d_in[27];
    const float* bT   = (const float*)d_in[28];
    float* out = (float*)d_out;

    void *p_xn, *p_xproj, *p_zs, *p_xpf, *p_xpb, *p_df, *p_dbk, *p_yf, *p_yb;
    void *p_Bpf, *p_Cpf, *p_Bpb, *p_Cpb, *p_wcf, *p_wcb;
    cudaGetSymbolAddress(&p_xn, g_xn);
    cudaGetSymbolAddress(&p_xproj, g_xproj);
    cudaGetSymbolAddress(&p_zs, g_zs);
    cudaGetSymbolAddress(&p_xpf, g_xpf);
    cudaGetSymbolAddress(&p_xpb, g_xpb);
    cudaGetSymbolAddress(&p_df, g_df);
    cudaGetSymbolAddress(&p_dbk, g_dbk);
    cudaGetSymbolAddress(&p_yf, g_yf);
    cudaGetSymbolAddress(&p_yb, g_yb);
    cudaGetSymbolAddress(&p_Bpf, g_Bpf);
    cudaGetSymbolAddress(&p_Cpf, g_Cpf);
    cudaGetSymbolAddress(&p_Bpb, g_Bpb);
    cudaGetSymbolAddress(&p_Cpb, g_Cpb);
    cudaGetSymbolAddress(&p_wcf, g_wcf);
    cudaGetSymbolAddress(&p_wcb, g_wcb);

    float* xn    = (float*)p_xn;
    float* xproj = (float*)p_xproj;
    float* zs    = (float*)p_zs;
    float* xpf   = (float*)p_xpf;
    float* xpb   = (float*)p_xpb;
    float* df    = (float*)p_df;
    float* dbk   = (float*)p_dbk;
    float* yf    = (float*)p_yf;
    float* yb    = (float*)p_yb;
    float* Bpf   = (float*)p_Bpf;
    float* Cpf   = (float*)p_Cpf;
    float* Bpb   = (float*)p_Bpb;
    float* Cpb   = (float*)p_Cpb;
    float* wcf   = (float*)p_wcf;
    float* wcb   = (float*)p_wcb;

    // 1. layernorm
    ln_kernel<<<BMr, 256>>>(t, ln_g, ln_b, xn);

    // 2. x_proj and silu(z)  (tf32 tensor cores)
    dim3 gEB(Ee/128, BMr/128);
    gemm_tc<0><<<gEB, 256>>>(xn, Wx, bx, nullptr, nullptr, xproj, Ee, Dd);
    gemm_tc<1><<<gEB, 256>>>(xn, Wz, bz, nullptr, nullptr, zs,    Ee, Dd);

    // 3. conv weight repack + convs (fused bias + silu)
    repack_conv<<<(Ee*Ee + 255)/256, 256>>>(Wcf, wcf);
    repack_conv<<<(Ee*Ee + 255)/256, 256>>>(Wcb, wcb);
    conv_tc<<<gEB, 256>>>(xproj, wcf, bcf, xpf);
    conv_tc<<<gEB, 256>>>(xproj, wcb, bcb, xpb);

    // 4. B/C projections
    bc_kernel<<<BMr/256, 256>>>(xpf, WBf, bBf, WCf, bCf, Bpf, Cpf);
    bc_kernel<<<BMr/256, 256>>>(xpb, WBb, bBb, WCb, bCb, Bpb, Cpb);

    // 5. Delta (softplus)
    gemm_tc<2><<<gEB, 256>>>(xpf, WDf, bDf, dbf, nullptr, df,  Ee, Ee);
    gemm_tc<2><<<gEB, 256>>>(xpb, WDb, bDb, dbb, nullptr, dbk, Ee, Ee);

    // 6. scans (both directions in one launch)
    scan_kernel<<<dim3(Ee/256, Bb, 2), 256>>>(xpf, df, Bpf, Cpf, Abf, yf,
                                              xpb, dbk, Bpb, Cpb, Abb, yb);

    // 7. gate multiply (reuse xproj as gated y)
    mul_kernel<<<2048, 256>>>((const float4*)yf, (const float4*)yb,
                              (const float4*)zs, (float4*)xproj,
                              (BMr * Ee) / 4);

    // 8. final projection + residual
    gemm_tc<0><<<dim3(Dd/128, BMr/128), 256>>>(xproj, WT, bT, nullptr, t, out, Dd, Ee);
}